// round 1
// baseline (speedup 1.0000x reference)
#include <cuda_runtime.h>
#include <math.h>

// Problem shape (fixed by setup_inputs)
#define SDIM 2048
#define RDIM 512
#define CDIM 64
// heads=8, c_hid=8, h*ch = 64

// ---------------- device scratch (no allocs allowed) ----------------
static __device__ float g_pool[RDIM * CDIM];            // masked sum of ln(x) over s, per (r,c)
static __device__ float g_msum[RDIM];                   // sum of mask over s, per r
static __device__ float g_kv[(size_t)RDIM * SDIM * 16]; // per (r,s): k[0..7], v[0..7]
static __device__ float g_ovec[RDIM * CDIM];            // per r: o[h*8+ch]

// ---------------- kernel Z: zero the accumulators --------------------
__global__ void k_zero() {
    int i = blockIdx.x * blockDim.x + threadIdx.x;
    if (i < RDIM * CDIM) g_pool[i] = 0.f;
    if (i < RDIM)        g_msum[i] = 0.f;
}

// ---------------- kernel A: LN + masked pool + K/V -------------------
// grid (SDIM/64, RDIM), 256 threads. Each block: one r, 64 consecutive s rows.
__global__ void __launch_bounds__(256) k_pool_kv(
    const float* __restrict__ m, const float* __restrict__ mask,
    const float* __restrict__ ln_w, const float* __restrict__ ln_b,
    const float* __restrict__ wk, const float* __restrict__ wv)
{
    __shared__ float s_xnT[CDIM][68];   // transposed: [c][row], padded
    __shared__ float s_wkv[CDIM][16];   // [c][j]: j<8 -> wk, j>=8 -> wv

    const int r   = blockIdx.y;
    const int s0  = blockIdx.x * 64;
    const int tid = threadIdx.x;
    const int lane = tid & 31;
    const int w    = tid >> 5;

    for (int i = tid; i < CDIM * 8; i += 256) {
        s_wkv[i >> 3][(i & 7)]     = wk[i];
        s_wkv[i >> 3][(i & 7) + 8] = wv[i];
    }

    const float lw0 = ln_w[lane], lw1 = ln_w[lane + 32];
    const float lb0 = ln_b[lane], lb1 = ln_b[lane + 32];

    float p0 = 0.f, p1 = 0.f, pm = 0.f;
    #pragma unroll
    for (int i = 0; i < 8; ++i) {
        const int row = w * 8 + i;
        const int s   = s0 + row;
        const float* mp = m + (s * RDIM + r) * CDIM;
        float x0 = mp[lane];
        float x1 = mp[lane + 32];
        float mv = __ldg(&mask[s * RDIM + r]);

        float sum = x0 + x1;
        #pragma unroll
        for (int o = 16; o; o >>= 1) sum += __shfl_xor_sync(0xffffffffu, sum, o);
        float mu = sum * (1.f / 64.f);
        float d0 = x0 - mu, d1 = x1 - mu;
        float vv = d0 * d0 + d1 * d1;
        #pragma unroll
        for (int o = 16; o; o >>= 1) vv += __shfl_xor_sync(0xffffffffu, vv, o);
        float rstd = rsqrtf(vv * (1.f / 64.f) + 1e-5f);
        float xn0 = d0 * rstd * lw0 + lb0;
        float xn1 = d1 * rstd * lw1 + lb1;

        s_xnT[lane][row]      = xn0;
        s_xnT[lane + 32][row] = xn1;
        p0 += xn0 * mv;
        p1 += xn1 * mv;
        pm += mv;
    }
    atomicAdd(&g_pool[r * CDIM + lane],      p0);
    atomicAdd(&g_pool[r * CDIM + lane + 32], p1);
    if (lane == 0) atomicAdd(&g_msum[r], pm);
    __syncthreads();

    // K/V GEMM: [64 rows x 64 c] @ [64 c x 16 j]
    const int rg = lane & 1;          // row sub-group
    const int cg = lane >> 1;         // output col 0..15
    const int row0 = w * 8 + rg * 4;
    float a0 = 0.f, a1 = 0.f, a2 = 0.f, a3 = 0.f;
    #pragma unroll 8
    for (int c = 0; c < 64; ++c) {
        float4 xv = *(const float4*)&s_xnT[c][row0];
        float ww  = s_wkv[c][cg];
        a0 += xv.x * ww; a1 += xv.y * ww; a2 += xv.z * ww; a3 += xv.w * ww;
    }
    float* kvp = g_kv + ((size_t)r * SDIM + s0 + row0) * 16 + cg;
    kvp[0]  = a0;
    kvp[16] = a1;
    kvp[32] = a2;
    kvp[48] = a3;
}

// ---------------- kernel B: q, softmax over S, o ---------------------
// grid (RDIM), 256 threads: warp h handles head h; lane strides over s.
__global__ void __launch_bounds__(256) k_attn(
    const float* __restrict__ mask, const float* __restrict__ wq)
{
    const int r   = blockIdx.x;
    const int tid = threadIdx.x;
    const int lane = tid & 31;
    const int h    = tid >> 5;

    __shared__ float s_p[64];
    if (tid < 64) s_p[tid] = g_pool[r * 64 + tid] / (g_msum[r] + 1e-10f);
    __syncthreads();

    // q[h][0..7] = (pool @ wq) * 8^-0.5
    float q[8];
    float pc0 = s_p[lane], pc1 = s_p[lane + 32];
    #pragma unroll
    for (int j = 0; j < 8; ++j)
        q[j] = pc0 * wq[lane * 64 + h * 8 + j] + pc1 * wq[(lane + 32) * 64 + h * 8 + j];
    #pragma unroll
    for (int o = 16; o; o >>= 1) {
        #pragma unroll
        for (int j = 0; j < 8; ++j) q[j] += __shfl_xor_sync(0xffffffffu, q[j], o);
    }
    #pragma unroll
    for (int j = 0; j < 8; ++j) q[j] *= 0.35355339059327373f;

    const float LOG2E = 1.4426950408889634f;
    float M = -1e30f, L = 0.f;
    float acc[8];
    #pragma unroll
    for (int j = 0; j < 8; ++j) acc[j] = 0.f;

    for (int t = 0; t < SDIM / 32; ++t) {
        int s = t * 32 + lane;
        const float4* kv = (const float4*)(g_kv + ((size_t)r * SDIM + s) * 16);
        float4 k0 = kv[0], k1 = kv[1];
        float4 v0 = kv[2], v1 = kv[3];
        float mv = __ldg(&mask[s * RDIM + r]);
        float logit = q[0]*k0.x + q[1]*k0.y + q[2]*k0.z + q[3]*k0.w
                    + q[4]*k1.x + q[5]*k1.y + q[6]*k1.z + q[7]*k1.w
                    + 1e9f * (mv - 1.f);
        float nM = fmaxf(M, logit);
        float sc = exp2f((M - nM) * LOG2E);
        float p  = exp2f((logit - nM) * LOG2E);
        L = L * sc + p;
        acc[0] = acc[0]*sc + p*v0.x; acc[1] = acc[1]*sc + p*v0.y;
        acc[2] = acc[2]*sc + p*v0.z; acc[3] = acc[3]*sc + p*v0.w;
        acc[4] = acc[4]*sc + p*v1.x; acc[5] = acc[5]*sc + p*v1.y;
        acc[6] = acc[6]*sc + p*v1.z; acc[7] = acc[7]*sc + p*v1.w;
        M = nM;
    }
    // merge lanes
    float Mm = M;
    #pragma unroll
    for (int o = 16; o; o >>= 1) Mm = fmaxf(Mm, __shfl_xor_sync(0xffffffffu, Mm, o));
    float sc = exp2f((M - Mm) * LOG2E);
    L *= sc;
    #pragma unroll
    for (int j = 0; j < 8; ++j) acc[j] *= sc;
    #pragma unroll
    for (int o = 16; o; o >>= 1) {
        L += __shfl_xor_sync(0xffffffffu, L, o);
        #pragma unroll
        for (int j = 0; j < 8; ++j) acc[j] += __shfl_xor_sync(0xffffffffu, acc[j], o);
    }
    if (lane == 0) {
        float inv = 1.f / L;
        #pragma unroll
        for (int j = 0; j < 8; ++j) g_ovec[r * 64 + h * 8 + j] = acc[j] * inv;
    }
}

// ---------------- kernel C: LN -> gate GEMM -> output GEMM -----------
// grid (SDIM/64, RDIM), 256 threads, dynamic smem.
__global__ void __launch_bounds__(256) k_out(
    const float* __restrict__ m,
    const float* __restrict__ ln_w, const float* __restrict__ ln_b,
    const float* __restrict__ wg, const float* __restrict__ bg,
    const float* __restrict__ wo, const float* __restrict__ bo,
    float* __restrict__ out)
{
    extern __shared__ float sm[];
    float (*s_xnT)[68] = (float(*)[68])sm;              // [c][row]
    float (*s_gT)[68]  = (float(*)[68])(sm + 64 * 68);  // [j][row]
    float* s_wg = sm + 2 * 64 * 68;                     // [c*64+j]
    float* s_wo = s_wg + 64 * 64;                       // folded o[j]*wo[j][c]
    float* s_bg = s_wo + 64 * 64;                       // [64]

    const int r   = blockIdx.y;
    const int s0  = blockIdx.x * 64;
    const int tid = threadIdx.x;
    const int lane = tid & 31;
    const int w    = tid >> 5;

    const float* ov = g_ovec + r * 64;
    for (int i = tid; i < 4096; i += 256) {
        s_wg[i] = wg[i];
        s_wo[i] = ov[i >> 6] * wo[i];
    }
    if (tid < 64) s_bg[tid] = bg[tid];

    // LayerNorm phase (warp-per-row)
    const float lw0 = ln_w[lane], lw1 = ln_w[lane + 32];
    const float lb0 = ln_b[lane], lb1 = ln_b[lane + 32];
    #pragma unroll
    for (int i = 0; i < 8; ++i) {
        const int row = w * 8 + i;
        const int s   = s0 + row;
        const float* mp = m + (s * RDIM + r) * CDIM;
        float x0 = mp[lane];
        float x1 = mp[lane + 32];
        float sum = x0 + x1;
        #pragma unroll
        for (int o = 16; o; o >>= 1) sum += __shfl_xor_sync(0xffffffffu, sum, o);
        float mu = sum * (1.f / 64.f);
        float d0 = x0 - mu, d1 = x1 - mu;
        float vv = d0 * d0 + d1 * d1;
        #pragma unroll
        for (int o = 16; o; o >>= 1) vv += __shfl_xor_sync(0xffffffffu, vv, o);
        float rstd = rsqrtf(vv * (1.f / 64.f) + 1e-5f);
        s_xnT[lane][row]      = d0 * rstd * lw0 + lb0;
        s_xnT[lane + 32][row] = d1 * rstd * lw1 + lb1;
    }
    __syncthreads();

    const int rg = lane & 1;
    const int jg = lane >> 1;
    const int row0 = w * 8 + rg * 4;
    const int j0   = jg * 4;

    // GEMM1: G = sigmoid(XN @ wg + bg); store transposed gT[j][row]
    float acc[4][4];   // [jj][ri]
    #pragma unroll
    for (int a = 0; a < 4; ++a)
        #pragma unroll
        for (int b = 0; b < 4; ++b) acc[a][b] = 0.f;

    #pragma unroll 8
    for (int c = 0; c < 64; ++c) {
        float4 xv = *(const float4*)&s_xnT[c][row0];
        float4 wv = *(const float4*)&s_wg[c * 64 + j0];
        acc[0][0] += wv.x*xv.x; acc[0][1] += wv.x*xv.y; acc[0][2] += wv.x*xv.z; acc[0][3] += wv.x*xv.w;
        acc[1][0] += wv.y*xv.x; acc[1][1] += wv.y*xv.y; acc[1][2] += wv.y*xv.z; acc[1][3] += wv.y*xv.w;
        acc[2][0] += wv.z*xv.x; acc[2][1] += wv.z*xv.y; acc[2][2] += wv.z*xv.z; acc[2][3] += wv.z*xv.w;
        acc[3][0] += wv.w*xv.x; acc[3][1] += wv.w*xv.y; acc[3][2] += wv.w*xv.z; acc[3][3] += wv.w*xv.w;
    }
    #pragma unroll
    for (int jj = 0; jj < 4; ++jj) {
        float b = s_bg[j0 + jj];
        float4 g4;
        g4.x = __fdividef(1.f, 1.f + __expf(-(acc[jj][0] + b)));
        g4.y = __fdividef(1.f, 1.f + __expf(-(acc[jj][1] + b)));
        g4.z = __fdividef(1.f, 1.f + __expf(-(acc[jj][2] + b)));
        g4.w = __fdividef(1.f, 1.f + __expf(-(acc[jj][3] + b)));
        *(float4*)&s_gT[j0 + jj][row0] = g4;
    }
    __syncthreads();

    // GEMM2: out = G @ (o (.) wo) + bo
    float acc2[4][4];  // [ri][cc]
    #pragma unroll
    for (int a = 0; a < 4; ++a)
        #pragma unroll
        for (int b = 0; b < 4; ++b) acc2[a][b] = 0.f;

    #pragma unroll 8
    for (int j = 0; j < 64; ++j) {
        float4 gv = *(const float4*)&s_gT[j][row0];
        float4 wv = *(const float4*)&s_wo[j * 64 + j0];
        acc2[0][0] += gv.x*wv.x; acc2[0][1] += gv.x*wv.y; acc2[0][2] += gv.x*wv.z; acc2[0][3] += gv.x*wv.w;
        acc2[1][0] += gv.y*wv.x; acc2[1][1] += gv.y*wv.y; acc2[1][2] += gv.y*wv.z; acc2[1][3] += gv.y*wv.w;
        acc2[2][0] += gv.z*wv.x; acc2[2][1] += gv.z*wv.y; acc2[2][2] += gv.z*wv.z; acc2[2][3] += gv.z*wv.w;
        acc2[3][0] += gv.w*wv.x; acc2[3][1] += gv.w*wv.y; acc2[3][2] += gv.w*wv.z; acc2[3][3] += gv.w*wv.w;
    }
    float4 bo4 = *(const float4*)&bo[j0];
    #pragma unroll
    for (int ri = 0; ri < 4; ++ri) {
        const int s = s0 + row0 + ri;
        float4 o4;
        o4.x = acc2[ri][0] + bo4.x;
        o4.y = acc2[ri][1] + bo4.y;
        o4.z = acc2[ri][2] + bo4.z;
        o4.w = acc2[ri][3] + bo4.w;
        *(float4*)&out[(s * RDIM + r) * CDIM + j0] = o4;
    }
}

// ---------------------------------------------------------------------
extern "C" void kernel_launch(void* const* d_in, const int* in_sizes, int n_in,
                              void* d_out, int out_size) {
    const float* m    = (const float*)d_in[0];
    const float* mask = (const float*)d_in[1];
    const float* ln_w = (const float*)d_in[2];
    const float* ln_b = (const float*)d_in[3];
    const float* wq   = (const float*)d_in[4];
    const float* wk   = (const float*)d_in[5];
    const float* wv   = (const float*)d_in[6];
    const float* wg   = (const float*)d_in[7];
    const float* bg   = (const float*)d_in[8];
    const float* wo   = (const float*)d_in[9];
    const float* bo   = (const float*)d_in[10];
    float* out = (float*)d_out;

    const int SMEM_C = (2 * 64 * 68 + 2 * 64 * 64 + 64) * (int)sizeof(float); // 67840 B
    cudaFuncSetAttribute(k_out, cudaFuncAttributeMaxDynamicSharedMemorySize, SMEM_C);

    k_zero<<<128, 256>>>();
    dim3 gTiles(SDIM / 64, RDIM);
    k_pool_kv<<<gTiles, 256>>>(m, mask, ln_w, ln_b, wk, wv);
    k_attn<<<RDIM, 256>>>(mask, wq);
    k_out<<<gTiles, 256, SMEM_C>>>(m, ln_w, ln_b, wg, bg, wo, bo, out);
}